// round 4
// baseline (speedup 1.0000x reference)
#include <cuda_runtime.h>
#include <cuda_bf16.h>
#include <cstdint>

// Output: 79,950,000 f32 elements, flat concat of (all cast to f32):
//   [0, 76.8M)        fill_feats = x rows then gen_feats rows
//   [76.8M, 78.9M)    fill_edges row-major [2, M]: src row then dst row
//   [78.9M, 79.95M)   edge_mask (0.0 / 1.0)
// M = E + N*P.  edge_index input is int32 (JAX x64 disabled downcasts int64).

__global__ void feats_copy_kernel(const float4* __restrict__ x,
                                  const float4* __restrict__ g,
                                  float4* __restrict__ out,
                                  int nx4, int total4)
{
    int i = blockIdx.x * blockDim.x + threadIdx.x;
    if (i >= total4) return;
    if (i < nx4) out[i] = x[i];
    else         out[i] = g[i - nx4];
}

__global__ void edges_mask_kernel(const int* __restrict__ ei,   // [2, E] int32
                                  const float* __restrict__ pm, // [N]
                                  float* __restrict__ out_e,    // [3*M] region
                                  int E, int M, int N, int P)
{
    int j = blockIdx.x * blockDim.x + threadIdx.x;
    if (j >= M) return;

    float s, d, m;
    if (j < E) {
        s = (float)ei[j];        // edge_index[0][j]
        d = (float)ei[E + j];    // edge_index[1][j]
        m = 1.0f;
    } else {
        int jp = j - E;          // synthetic edge index in [0, N*P)
        int i  = jp / P;         // source node
        s = (float)i;
        d = (float)(N + jp);     // num_node + i*num_pred + k
        // deg = clip(round(pred_missing[i]), 0, P); jnp.round = half-to-even = rintf
        int deg = (int)rintf(pm[i]);
        deg = max(0, min(deg, P));
        m = ((jp - i * P) < deg) ? 1.0f : 0.0f;
    }
    out_e[j]         = s;   // fill_edges row 0
    out_e[M + j]     = d;   // fill_edges row 1
    out_e[2 * M + j] = m;   // edge_mask
}

extern "C" void kernel_launch(void* const* d_in, const int* in_sizes, int n_in,
                              void* d_out, int out_size)
{
    const float* x   = (const float*)d_in[0];   // [N, F] f32
    const int*   ei  = (const int*)d_in[1];     // [2, E] int32
    const float* pm  = (const float*)d_in[2];   // [N] f32
    const float* gen = (const float*)d_in[3];   // [N, P*F] f32

    const int N   = in_sizes[2];
    const int E   = in_sizes[1] / 2;
    const int P   = in_sizes[3] / in_sizes[0];  // num_pred
    const int NFx = in_sizes[0];                // N*F
    const int NFg = in_sizes[3];                // N*P*F
    const int M   = E + N * P;

    float* out = (float*)d_out;

    // 1) feats copy, float4 vectorized (NFx, NFg multiples of 4)
    {
        const int nx4    = NFx / 4;
        const int total4 = (NFx + NFg) / 4;
        const int threads = 256;
        const int blocks  = (total4 + threads - 1) / threads;
        feats_copy_kernel<<<blocks, threads>>>((const float4*)x, (const float4*)gen,
                                               (float4*)out, nx4, total4);
    }

    // 2) edges + mask (all f32)
    {
        float* out_e = out + (size_t)(NFx + NFg);
        const int threads = 256;
        const int blocks  = (M + threads - 1) / threads;
        edges_mask_kernel<<<blocks, threads>>>(ei, pm, out_e, E, M, N, P);
    }
}